// round 1
// baseline (speedup 1.0000x reference)
#include <cuda_runtime.h>

#define DIM 256
#define HEADS 8
#define HD 32
#define N_TOK 64
#define IMG 256
#define BATCH 4
#define NWIN 1024          // windows per batch image (32*32)
#define NPIX 262144        // 4*256*256
#define SCALE 0.17677669529663687f

// scratch (static device globals: allocation-free per harness rules)
__device__ __align__(256) float g_qkv[201326592];  // [4096 win][3][64 tok][256 ch]  (805 MB)
__device__ __align__(256) float g_o[67108864];     // [B][H][W][C] pixel-major       (268 MB)

// ---------------------------------------------------------------------------
// GEMM: C[m, n] = sum_k A[m,k] * B[n,k]   (A: [M,256], B: [N,256] row-major)
// QKV=true : scatter epilogue with roll(+4,+4) + window partition into g_qkv
// QKV=false: dense epilogue + bias into C
// block: 256 thr, 64x64 tile, 4x4 micro-tile
// ---------------------------------------------------------------------------
template <bool QKV>
__global__ __launch_bounds__(256) void gemm_kernel(const float* __restrict__ A,
                                                   const float* __restrict__ B,
                                                   const float* __restrict__ bias,
                                                   float* __restrict__ C) {
    __shared__ float sA[32][68];   // [k][m], +4 pad keeps 16B alignment of frags
    __shared__ float sB[32][68];   // [k][n]
    const int m0 = blockIdx.x * 64;
    const int n0 = blockIdx.y * 64;
    const int tid = threadIdx.x;
    const int ty = tid >> 4, tx = tid & 15;

    float acc[4][4] = {};

    for (int k0 = 0; k0 < DIM; k0 += 32) {
#pragma unroll
        for (int q = 0; q < 2; ++q) {
            int f = tid + q * 256;
            int row = f >> 3;
            int c4 = (f & 7) << 2;
            float4 va = *(const float4*)(A + (size_t)(m0 + row) * DIM + k0 + c4);
            sA[c4 + 0][row] = va.x; sA[c4 + 1][row] = va.y;
            sA[c4 + 2][row] = va.z; sA[c4 + 3][row] = va.w;
            float4 vb = *(const float4*)(B + (size_t)(n0 + row) * DIM + k0 + c4);
            sB[c4 + 0][row] = vb.x; sB[c4 + 1][row] = vb.y;
            sB[c4 + 2][row] = vb.z; sB[c4 + 3][row] = vb.w;
        }
        __syncthreads();
#pragma unroll
        for (int kk = 0; kk < 32; ++kk) {
            float4 a4 = *(const float4*)&sA[kk][ty * 4];
            float4 b4 = *(const float4*)&sB[kk][tx * 4];
            float av[4] = {a4.x, a4.y, a4.z, a4.w};
            float bv[4] = {b4.x, b4.y, b4.z, b4.w};
#pragma unroll
            for (int i = 0; i < 4; ++i)
#pragma unroll
                for (int j = 0; j < 4; ++j)
                    acc[i][j] = fmaf(av[i], bv[j], acc[i][j]);
        }
        __syncthreads();
    }

    if (QKV) {
        const int t = n0 >> 8;                 // q/k/v selector (tile never crosses)
        const int cb = (n0 & 255) + tx * 4;    // channel within [0,256)
#pragma unroll
        for (int i = 0; i < 4; ++i) {
            int p = m0 + ty * 4 + i;
            int b = p >> 16;
            int h = (p >> 8) & 255;
            int w = p & 255;
            int hs = (h + 4) & 255;            // cyclic shift +4
            int ws = (w + 4) & 255;
            int win = b * NWIN + ((hs >> 3) << 5) + (ws >> 3);
            int n = ((hs & 7) << 3) | (ws & 7);
            float4 o = make_float4(acc[i][0], acc[i][1], acc[i][2], acc[i][3]);
            *(float4*)(C + (((size_t)win * 3 + t) * N_TOK + n) * DIM + cb) = o;
        }
    } else {
        float4 bi = *(const float4*)(bias + n0 + tx * 4);
#pragma unroll
        for (int i = 0; i < 4; ++i) {
            int p = m0 + ty * 4 + i;
            float4 o = make_float4(acc[i][0] + bi.x, acc[i][1] + bi.y,
                                   acc[i][2] + bi.z, acc[i][3] + bi.w);
            *(float4*)(C + (size_t)p * DIM + n0 + tx * 4) = o;
        }
    }
}

// ---------------------------------------------------------------------------
// Windowed attention: 1 block per window, 512 threads = (head, query row).
// K,V staged in 128KB dynamic smem; scores register-resident; mask analytic.
// Output store fuses window unpartition + roll(-4,-4) into pixel-major g_o.
// ---------------------------------------------------------------------------
extern __shared__ float attn_smem[];

__global__ __launch_bounds__(512) void attn_kernel() {
    float* sK = attn_smem;               // [64][256]
    float* sV = attn_smem + 64 * 256;    // [64][256]
    __shared__ int sReg[64];

    const int win = blockIdx.x;          // 0..4095
    const int wl = win & 1023;           // window within image
    const int tid = threadIdx.x;
    const int head = tid >> 6;
    const int row = tid & 63;

    const float* base = g_qkv + (size_t)win * 3 * N_TOK * DIM;

    // cooperative copy K, V -> smem (coalesced float4)
    {
        const float4* k4 = (const float4*)(base + N_TOK * DIM);
        const float4* v4 = (const float4*)(base + 2 * N_TOK * DIM);
        float4* sK4 = (float4*)sK;
        float4* sV4 = (float4*)sV;
#pragma unroll
        for (int i = 0; i < 8; ++i) {
            int idx = tid + i * 512;
            sK4[idx] = k4[idx];
            sV4[idx] = v4[idx];
        }
    }
    // region ids for Swin shift mask (nonzero only for edge windows)
    if (tid < 64) {
        int hs = ((wl >> 5) << 3) + (tid >> 3);
        int ws = ((wl & 31) << 3) + (tid & 7);
        int rh = (hs < 248) ? 0 : (hs < 252 ? 1 : 2);
        int rw = (ws < 248) ? 0 : (ws < 252 ? 1 : 2);
        sReg[tid] = rh * 3 + rw;
    }
    __syncthreads();

    // q row -> regs
    float q[32];
    {
        const float4* qr = (const float4*)(base + (size_t)row * DIM + head * HD);
#pragma unroll
        for (int d4 = 0; d4 < 8; ++d4) {
            float4 t = qr[d4];
            q[d4 * 4 + 0] = t.x; q[d4 * 4 + 1] = t.y;
            q[d4 * 4 + 2] = t.z; q[d4 * 4 + 3] = t.w;
        }
    }
    const int myreg = sReg[row];

    // scores
    float s[64];
#pragma unroll
    for (int m = 0; m < 64; ++m) {
        const float4* kr = (const float4*)(sK + m * DIM + head * HD);
        float a = 0.f;
#pragma unroll
        for (int d4 = 0; d4 < 8; ++d4) {
            float4 kv = kr[d4];
            a = fmaf(q[d4 * 4 + 0], kv.x, a);
            a = fmaf(q[d4 * 4 + 1], kv.y, a);
            a = fmaf(q[d4 * 4 + 2], kv.z, a);
            a = fmaf(q[d4 * 4 + 3], kv.w, a);
        }
        s[m] = a * SCALE + ((sReg[m] == myreg) ? 0.f : -100.f);
    }

    // softmax (register-resident)
    float mx = s[0];
#pragma unroll
    for (int m = 1; m < 64; ++m) mx = fmaxf(mx, s[m]);
    float sum = 0.f;
#pragma unroll
    for (int m = 0; m < 64; ++m) {
        s[m] = __expf(s[m] - mx);
        sum += s[m];
    }
    const float inv = 1.f / sum;

    // O = P @ V
    float o[32];
#pragma unroll
    for (int d = 0; d < 32; ++d) o[d] = 0.f;
#pragma unroll
    for (int m = 0; m < 64; ++m) {
        const float4* vr = (const float4*)(sV + m * DIM + head * HD);
        float p = s[m];
#pragma unroll
        for (int d4 = 0; d4 < 8; ++d4) {
            float4 vv = vr[d4];
            o[d4 * 4 + 0] = fmaf(p, vv.x, o[d4 * 4 + 0]);
            o[d4 * 4 + 1] = fmaf(p, vv.y, o[d4 * 4 + 1]);
            o[d4 * 4 + 2] = fmaf(p, vv.z, o[d4 * 4 + 2]);
            o[d4 * 4 + 3] = fmaf(p, vv.w, o[d4 * 4 + 3]);
        }
    }

    // store: unpartition + reverse shift, pixel-major (one 128B line per thread)
    {
        int b = win >> 10;
        int hs = ((wl >> 5) << 3) + (row >> 3);
        int ws = ((wl & 31) << 3) + (row & 7);
        int h = (hs + 252) & 255;
        int w = (ws + 252) & 255;
        float* dst = g_o + (((size_t)b * IMG + h) * IMG + w) * DIM + head * HD;
#pragma unroll
        for (int d4 = 0; d4 < 8; ++d4) {
            *(float4*)(dst + d4 * 4) =
                make_float4(o[d4 * 4 + 0] * inv, o[d4 * 4 + 1] * inv,
                            o[d4 * 4 + 2] * inv, o[d4 * 4 + 3] * inv);
        }
    }
}

// ---------------------------------------------------------------------------

extern "C" void kernel_launch(void* const* d_in, const int* in_sizes, int n_in,
                              void* d_out, int out_size) {
    const float* x      = (const float*)d_in[0];
    const float* qkv_w  = (const float*)d_in[1];
    const float* proj_w = (const float*)d_in[2];
    const float* proj_b = (const float*)d_in[3];
    float* out = (float*)d_out;

    float* qkv_ptr = nullptr;
    float* o_ptr = nullptr;
    cudaGetSymbolAddress((void**)&qkv_ptr, g_qkv);
    cudaGetSymbolAddress((void**)&o_ptr, g_o);

    cudaFuncSetAttribute(attn_kernel, cudaFuncAttributeMaxDynamicSharedMemorySize,
                         131072);

    // 1) qkv projection + shift + window partition
    gemm_kernel<true><<<dim3(NPIX / 64, (3 * DIM) / 64), 256>>>(x, qkv_w, nullptr,
                                                                qkv_ptr);
    // 2) shifted-window attention (+ unpartition + reverse shift)
    attn_kernel<<<BATCH * NWIN, 512, 131072>>>();
    // 3) output projection + bias
    gemm_kernel<false><<<dim3(NPIX / 64, DIM / 64), 256>>>(o_ptr, proj_w, proj_b,
                                                           out);
}

// round 3
// speedup vs baseline: 2.8805x; 2.8805x over previous
#include <cuda_runtime.h>
#include <cstdint>

#define DIM 256
#define HEADS 8
#define HD 32
#define N_TOK 64
#define IMG 256
#define BATCH 4
#define NWIN 1024
#define NPIX 262144
#define SCALE 0.17677669529663687f

// scratch (static device globals: allocation-free per harness rules)
__device__ __align__(256) float g_qkv[201326592];  // [4096 win][3][64 tok][256 ch]
__device__ __align__(256) float g_o[67108864];     // [B][H][W][C] pixel-major

extern __shared__ float dynsmem[];

__device__ __forceinline__ uint32_t to_tf32(float x) {
    uint32_t r;
    asm("cvt.rna.tf32.f32 %0, %1;" : "=r"(r) : "f"(x));
    return r;
}

__device__ __forceinline__ void mma_tf32(float c[4], const uint32_t a[4],
                                         uint32_t b0, uint32_t b1) {
    asm volatile(
        "mma.sync.aligned.m16n8k8.row.col.f32.tf32.tf32.f32 "
        "{%0,%1,%2,%3}, {%4,%5,%6,%7}, {%8,%9}, {%0,%1,%2,%3};"
        : "+f"(c[0]), "+f"(c[1]), "+f"(c[2]), "+f"(c[3])
        : "r"(a[0]), "r"(a[1]), "r"(a[2]), "r"(a[3]), "r"(b0), "r"(b1));
}

// ---------------------------------------------------------------------------
// tf32 mma.sync GEMM: C[m,n] = sum_k A[m,k]*B[n,k], K=256.
// CTA 128x256, 512 thr (16 warps, warp tile 32x64), K in 8 stages of 32,
// double-buffered smem, stride 36 floats (conflict-free frags).
// QKV=true : scatter epilogue (roll+4 + window partition) into g_qkv
// QKV=false: bias epilogue, dense row-major store
// ---------------------------------------------------------------------------
template <bool QKV>
__global__ __launch_bounds__(512, 1)
void mma_gemm(const float* __restrict__ A, const float* __restrict__ Bw,
              const float* __restrict__ bias, float* __restrict__ C) {
    float* sA = dynsmem;            // [2][128][36]
    float* sB = dynsmem + 9216;     // [2][256][36]

    const int tid = threadIdx.x;
    const int wid = tid >> 5, lane = tid & 31;
    const int g = lane >> 2, tig = lane & 3;
    const int warp_m = wid & 3, warp_n = wid >> 2;
    const int m0 = blockIdx.x * 128, n0 = blockIdx.y * 256;

    float acc[2][8][4];
#pragma unroll
    for (int i = 0; i < 2; ++i)
#pragma unroll
        for (int j = 0; j < 8; ++j)
#pragma unroll
            for (int c = 0; c < 4; ++c) acc[i][j][c] = 0.f;

    // per-thread fetch slots
    const int ar0 = tid >> 3, ac4 = tid & 7;          // A: rows tid>>3, tid>>3+64
    float4 fa[2], fb[4];

    auto fetch = [&](int k0) {
#pragma unroll
        for (int t = 0; t < 2; ++t)
            fa[t] = *(const float4*)(A + (size_t)(m0 + ar0 + t * 64) * DIM + k0 + ac4 * 4);
#pragma unroll
        for (int t = 0; t < 4; ++t)
            fb[t] = *(const float4*)(Bw + (size_t)(n0 + ar0 + t * 64) * DIM + k0 + ac4 * 4);
    };
    auto stage_store = [&](int buf) {
#pragma unroll
        for (int t = 0; t < 2; ++t) {
            uint32_t* p = (uint32_t*)(sA + buf * 4608 + (ar0 + t * 64) * 36 + ac4 * 4);
            uint4 v = make_uint4(to_tf32(fa[t].x), to_tf32(fa[t].y),
                                 to_tf32(fa[t].z), to_tf32(fa[t].w));
            *(uint4*)p = v;
        }
#pragma unroll
        for (int t = 0; t < 4; ++t) {
            uint32_t* p = (uint32_t*)(sB + buf * 9216 + (ar0 + t * 64) * 36 + ac4 * 4);
            uint4 v = make_uint4(to_tf32(fb[t].x), to_tf32(fb[t].y),
                                 to_tf32(fb[t].z), to_tf32(fb[t].w));
            *(uint4*)p = v;
        }
    };
    auto compute = [&](int buf) {
        const uint32_t* bA = (const uint32_t*)(sA + buf * 4608) + warp_m * 32 * 36;
        const uint32_t* bB = (const uint32_t*)(sB + buf * 9216) + warp_n * 64 * 36;
#pragma unroll
        for (int k = 0; k < 32; k += 8) {
            uint32_t af[2][4];
#pragma unroll
            for (int mt = 0; mt < 2; ++mt) {
                const uint32_t* r0 = bA + (mt * 16 + g) * 36 + k;
                af[mt][0] = r0[tig];
                af[mt][1] = r0[8 * 36 + tig];
                af[mt][2] = r0[tig + 4];
                af[mt][3] = r0[8 * 36 + tig + 4];
            }
#pragma unroll
            for (int nt = 0; nt < 8; ++nt) {
                const uint32_t* rb = bB + (nt * 8 + g) * 36 + k;
                uint32_t b0 = rb[tig], b1 = rb[tig + 4];
                mma_tf32(acc[0][nt], af[0], b0, b1);
                mma_tf32(acc[1][nt], af[1], b0, b1);
            }
        }
    };

    fetch(0);
    stage_store(0);
    __syncthreads();
#pragma unroll 1
    for (int s = 0; s < 8; ++s) {
        if (s < 7) fetch((s + 1) * 32);
        compute(s & 1);
        if (s < 7) {
            __syncthreads();
            stage_store((s + 1) & 1);
            __syncthreads();
        }
    }

    // epilogue: thread owns rows (warp_m*32 + mt*16 + half*8 + g), cols 2tig(+1)
#pragma unroll
    for (int mt = 0; mt < 2; ++mt) {
#pragma unroll
        for (int half = 0; half < 2; ++half) {
            int row = m0 + warp_m * 32 + mt * 16 + half * 8 + g;
            float* dst;
            if (QKV) {
                int b = row >> 16;
                int h = (row >> 8) & 255;
                int w = row & 255;
                int hs = (h + 4) & 255;   // cyclic shift +4
                int ws = (w + 4) & 255;
                int win = b * NWIN + ((hs >> 3) << 5) + (ws >> 3);
                int n = ((hs & 7) << 3) | (ws & 7);
                dst = C + (((size_t)win * 3 + blockIdx.y) * N_TOK + n) * DIM;
            } else {
                dst = C + (size_t)row * DIM;
            }
#pragma unroll
            for (int nt = 0; nt < 8; ++nt) {
                int col = warp_n * 64 + nt * 8 + 2 * tig;
                float2 v = make_float2(acc[mt][nt][half * 2], acc[mt][nt][half * 2 + 1]);
                if (!QKV) {
                    float2 bi = *(const float2*)(bias + col);
                    v.x += bi.x;
                    v.y += bi.y;
                }
                *(float2*)(dst + col) = v;
            }
        }
    }
}

// ---------------------------------------------------------------------------
// Windowed attention (unchanged, proven): 1 block/window, 512 thr =
// (head, query row); K,V in 128KB smem; analytic Swin mask; store fuses
// unpartition + roll(-4,-4) into pixel-major g_o.
// ---------------------------------------------------------------------------
__global__ __launch_bounds__(512) void attn_kernel() {
    float* sK = dynsmem;               // [64][256]
    float* sV = dynsmem + 64 * 256;    // [64][256]
    __shared__ int sReg[64];

    const int win = blockIdx.x;
    const int wl = win & 1023;
    const int tid = threadIdx.x;
    const int head = tid >> 6;
    const int row = tid & 63;

    const float* base = g_qkv + (size_t)win * 3 * N_TOK * DIM;

    {
        const float4* k4 = (const float4*)(base + N_TOK * DIM);
        const float4* v4 = (const float4*)(base + 2 * N_TOK * DIM);
        float4* sK4 = (float4*)sK;
        float4* sV4 = (float4*)sV;
#pragma unroll
        for (int i = 0; i < 8; ++i) {
            int idx = tid + i * 512;
            sK4[idx] = k4[idx];
            sV4[idx] = v4[idx];
        }
    }
    if (tid < 64) {
        int hs = ((wl >> 5) << 3) + (tid >> 3);
        int ws = ((wl & 31) << 3) + (tid & 7);
        int rh = (hs < 248) ? 0 : (hs < 252 ? 1 : 2);
        int rw = (ws < 248) ? 0 : (ws < 252 ? 1 : 2);
        sReg[tid] = rh * 3 + rw;
    }
    __syncthreads();

    float q[32];
    {
        const float4* qr = (const float4*)(base + (size_t)row * DIM + head * HD);
#pragma unroll
        for (int d4 = 0; d4 < 8; ++d4) {
            float4 t = qr[d4];
            q[d4 * 4 + 0] = t.x; q[d4 * 4 + 1] = t.y;
            q[d4 * 4 + 2] = t.z; q[d4 * 4 + 3] = t.w;
        }
    }
    const int myreg = sReg[row];

    float s[64];
#pragma unroll
    for (int m = 0; m < 64; ++m) {
        const float4* kr = (const float4*)(sK + m * DIM + head * HD);
        float a = 0.f;
#pragma unroll
        for (int d4 = 0; d4 < 8; ++d4) {
            float4 kv = kr[d4];
            a = fmaf(q[d4 * 4 + 0], kv.x, a);
            a = fmaf(q[d4 * 4 + 1], kv.y, a);
            a = fmaf(q[d4 * 4 + 2], kv.z, a);
            a = fmaf(q[d4 * 4 + 3], kv.w, a);
        }
        s[m] = a * SCALE + ((sReg[m] == myreg) ? 0.f : -100.f);
    }

    float mx = s[0];
#pragma unroll
    for (int m = 1; m < 64; ++m) mx = fmaxf(mx, s[m]);
    float sum = 0.f;
#pragma unroll
    for (int m = 0; m < 64; ++m) {
        s[m] = __expf(s[m] - mx);
        sum += s[m];
    }
    const float inv = 1.f / sum;

    float o[32];
#pragma unroll
    for (int d = 0; d < 32; ++d) o[d] = 0.f;
#pragma unroll
    for (int m = 0; m < 64; ++m) {
        const float4* vr = (const float4*)(sV + m * DIM + head * HD);
        float pm = s[m];
#pragma unroll
        for (int d4 = 0; d4 < 8; ++d4) {
            float4 vv = vr[d4];
            o[d4 * 4 + 0] = fmaf(pm, vv.x, o[d4 * 4 + 0]);
            o[d4 * 4 + 1] = fmaf(pm, vv.y, o[d4 * 4 + 1]);
            o[d4 * 4 + 2] = fmaf(pm, vv.z, o[d4 * 4 + 2]);
            o[d4 * 4 + 3] = fmaf(pm, vv.w, o[d4 * 4 + 3]);
        }
    }

    {
        int b = win >> 10;
        int hs = ((wl >> 5) << 3) + (row >> 3);
        int ws = ((wl & 31) << 3) + (row & 7);
        int h = (hs + 252) & 255;
        int w = (ws + 252) & 255;
        float* dst = g_o + (((size_t)b * IMG + h) * IMG + w) * DIM + head * HD;
#pragma unroll
        for (int d4 = 0; d4 < 8; ++d4) {
            *(float4*)(dst + d4 * 4) =
                make_float4(o[d4 * 4 + 0] * inv, o[d4 * 4 + 1] * inv,
                            o[d4 * 4 + 2] * inv, o[d4 * 4 + 3] * inv);
        }
    }
}

// ---------------------------------------------------------------------------

extern "C" void kernel_launch(void* const* d_in, const int* in_sizes, int n_in,
                              void* d_out, int out_size) {
    const float* x      = (const float*)d_in[0];
    const float* qkv_w  = (const float*)d_in[1];
    const float* proj_w = (const float*)d_in[2];
    const float* proj_b = (const float*)d_in[3];
    float* out = (float*)d_out;

    float* qkv_ptr = nullptr;
    float* o_ptr = nullptr;
    cudaGetSymbolAddress((void**)&qkv_ptr, g_qkv);
    cudaGetSymbolAddress((void**)&o_ptr, g_o);

    const int gemm_smem = (9216 + 18432) * 4;   // 110592 B
    cudaFuncSetAttribute(mma_gemm<true>, cudaFuncAttributeMaxDynamicSharedMemorySize,
                         gemm_smem);
    cudaFuncSetAttribute(mma_gemm<false>, cudaFuncAttributeMaxDynamicSharedMemorySize,
                         gemm_smem);
    cudaFuncSetAttribute(attn_kernel, cudaFuncAttributeMaxDynamicSharedMemorySize,
                         131072);

    // 1) qkv projection (tf32 mma.sync) + shift + window partition
    mma_gemm<true><<<dim3(NPIX / 128, 3), 512, gemm_smem>>>(x, qkv_w, nullptr, qkv_ptr);
    // 2) shifted-window attention (+ unpartition + reverse shift)
    attn_kernel<<<BATCH * NWIN, 512, 131072>>>();
    // 3) output projection (tf32 mma.sync) + bias
    mma_gemm<false><<<dim3(NPIX / 128, 1), 512, gemm_smem>>>(o_ptr, proj_w, proj_b, out);
}

// round 4
// speedup vs baseline: 3.3942x; 1.1783x over previous
#include <cuda_runtime.h>
#include <cstdint>

#define DIM 256
#define HEADS 8
#define HD 32
#define N_TOK 64
#define IMG 256
#define BATCH 4
#define NWIN 1024
#define NPIX 262144
#define SCALE 0.17677669529663687f

// scratch (static device globals: allocation-free per harness rules)
__device__ __align__(256) float g_qkv[201326592];  // [4096 win][3][64 tok][256 ch]
__device__ __align__(256) float g_o[67108864];     // [B][H][W][C] pixel-major

extern __shared__ float dynsmem[];

__device__ __forceinline__ uint32_t to_tf32(float x) {
    uint32_t r;
    asm("cvt.rna.tf32.f32 %0, %1;" : "=r"(r) : "f"(x));
    return r;
}

__device__ __forceinline__ void mma_tf32(float c[4], const uint32_t a[4],
                                         uint32_t b0, uint32_t b1) {
    asm volatile(
        "mma.sync.aligned.m16n8k8.row.col.f32.tf32.tf32.f32 "
        "{%0,%1,%2,%3}, {%4,%5,%6,%7}, {%8,%9}, {%0,%1,%2,%3};"
        : "+f"(c[0]), "+f"(c[1]), "+f"(c[2]), "+f"(c[3])
        : "r"(a[0]), "r"(a[1]), "r"(a[2]), "r"(a[3]), "r"(b0), "r"(b1));
}

__device__ __forceinline__ uint32_t smem_u32(const void* p) {
    uint32_t a;
    asm("{ .reg .u64 t; cvta.to.shared.u64 t, %1; cvt.u32.u64 %0, t; }"
        : "=r"(a) : "l"(p));
    return a;
}

#define CP_ASYNC16(dst_u32, src) \
    asm volatile("cp.async.cg.shared.global [%0], [%1], 16;" \
                 :: "r"(dst_u32), "l"(src) : "memory")
#define CP_COMMIT() asm volatile("cp.async.commit_group;" ::: "memory")
#define CP_WAIT(n)  asm volatile("cp.async.wait_group %0;" :: "n"(n) : "memory")

// ---------------------------------------------------------------------------
// tf32 mma.sync GEMM: C[m,n] = sum_k A[m,k]*B[n,k], K=256.
// CTA 128x256, 256 thr (8 warps, warp tile 64x64), cp.async 4-stage pipeline,
// 8 K-stages of 32, smem rows padded to 36 floats (conflict-free frags),
// tf32 cvt at fragment load.
// QKV=true : scatter epilogue (roll+4 + window partition) into g_qkv
// QKV=false: bias epilogue, dense row-major store
// ---------------------------------------------------------------------------
template <bool QKV>
__global__ __launch_bounds__(256, 1)
void mma_gemm(const float* __restrict__ A, const float* __restrict__ Bw,
              const float* __restrict__ bias, float* __restrict__ C) {
    float* sA = dynsmem;                 // [4][128][36]
    float* sB = dynsmem + 4 * 128 * 36;  // [4][256][36]
    const uint32_t sA_u = smem_u32(sA);
    const uint32_t sB_u = smem_u32(sB);

    const int tid = threadIdx.x;
    const int wid = tid >> 5, lane = tid & 31;
    const int g = lane >> 2, tig = lane & 3;
    const int warp_m = wid & 1, warp_n = wid >> 1;
    const int m0 = blockIdx.x * 128, n0 = blockIdx.y * 256;
    const int ar0 = tid >> 3, ac4 = tid & 7;

    float acc[4][8][4];
#pragma unroll
    for (int i = 0; i < 4; ++i)
#pragma unroll
        for (int j = 0; j < 8; ++j)
#pragma unroll
            for (int c = 0; c < 4; ++c) acc[i][j][c] = 0.f;

    auto issue = [&](int s) {
        const int k0 = s * 32;
        const uint32_t ab = sA_u + (uint32_t)((s & 3) * 4608 + ac4 * 4) * 4u;
        const uint32_t bb = sB_u + (uint32_t)((s & 3) * 9216 + ac4 * 4) * 4u;
#pragma unroll
        for (int t = 0; t < 4; ++t)
            CP_ASYNC16(ab + (uint32_t)((ar0 + t * 32) * 36) * 4u,
                       A + (size_t)(m0 + ar0 + t * 32) * DIM + k0 + ac4 * 4);
#pragma unroll
        for (int t = 0; t < 8; ++t)
            CP_ASYNC16(bb + (uint32_t)((ar0 + t * 32) * 36) * 4u,
                       Bw + (size_t)(n0 + ar0 + t * 32) * DIM + k0 + ac4 * 4);
        CP_COMMIT();
    };

    issue(0); issue(1); issue(2);

#pragma unroll 1
    for (int s = 0; s < 8; ++s) {
        if (s < 6) { CP_WAIT(2); }
        else if (s == 6) { CP_WAIT(1); }
        else { CP_WAIT(0); }
        __syncthreads();
        if (s < 5) issue(s + 3);

        const float* bA = sA + (s & 3) * 4608 + warp_m * 64 * 36;
        const float* bB = sB + (s & 3) * 9216 + warp_n * 64 * 36;
#pragma unroll
        for (int k = 0; k < 32; k += 8) {
            uint32_t a[4][4];
#pragma unroll
            for (int mt = 0; mt < 4; ++mt) {
                const float* r0 = bA + (mt * 16 + g) * 36 + k;
                a[mt][0] = to_tf32(r0[tig]);
                a[mt][1] = to_tf32(r0[8 * 36 + tig]);
                a[mt][2] = to_tf32(r0[tig + 4]);
                a[mt][3] = to_tf32(r0[8 * 36 + tig + 4]);
            }
#pragma unroll
            for (int nt = 0; nt < 8; ++nt) {
                const float* rb = bB + (nt * 8 + g) * 36 + k;
                uint32_t b0 = to_tf32(rb[tig]);
                uint32_t b1 = to_tf32(rb[tig + 4]);
#pragma unroll
                for (int mt = 0; mt < 4; ++mt) mma_tf32(acc[mt][nt], a[mt], b0, b1);
            }
        }
        __syncthreads();
    }

    // epilogue
#pragma unroll
    for (int mt = 0; mt < 4; ++mt) {
#pragma unroll
        for (int e = 0; e < 2; ++e) {
            int row = m0 + warp_m * 64 + mt * 16 + e * 8 + g;
            float* dst;
            if (QKV) {
                int b = row >> 16;
                int h = (row >> 8) & 255;
                int w = row & 255;
                int hs = (h + 4) & 255;
                int ws = (w + 4) & 255;
                int win = b * NWIN + ((hs >> 3) << 5) + (ws >> 3);
                int n = ((hs & 7) << 3) | (ws & 7);
                dst = C + (((size_t)win * 3 + blockIdx.y) * N_TOK + n) * DIM;
            } else {
                dst = C + (size_t)row * DIM;
            }
#pragma unroll
            for (int nt = 0; nt < 8; ++nt) {
                int col = warp_n * 64 + nt * 8 + 2 * tig;
                float2 v = make_float2(acc[mt][nt][e * 2], acc[mt][nt][e * 2 + 1]);
                if (!QKV) {
                    float2 bi = *(const float2*)(bias + col);
                    v.x += bi.x; v.y += bi.y;
                }
                *(float2*)(dst + col) = v;
            }
        }
    }
}

// ---------------------------------------------------------------------------
// Tensor-core windowed attention: 1 block/window (256 thr), warp w = head w.
// Q,K,V cvt'd to tf32 in smem per head: [Q 64x36 | K 64x36 | V 64x36] blocks
// (6912 floats/head). S = Q K^T and O = P V via m16n8k8 tf32 mma. Register
// softmax (quad shuffles); P overlays dead Q/K smem (64x68, conflict-free).
// Store fuses unpartition + roll(-4,-4) into pixel-major g_o.
// ---------------------------------------------------------------------------
__global__ __launch_bounds__(256, 1) void attn_kernel() {
    __shared__ int sReg[64];
    const int win = blockIdx.x;
    const int wl = win & 1023;
    const int tid = threadIdx.x;
    const int wid = tid >> 5, lane = tid & 31;
    const int g = lane >> 2, tig = lane & 3;

    const float* base = g_qkv + (size_t)win * 3 * N_TOK * DIM;

    // cooperative load + tf32 cvt: Q,K,V -> per-head smem blocks
#pragma unroll
    for (int m = 0; m < 3; ++m) {
        const float4* src = (const float4*)(base + m * N_TOK * DIM);
#pragma unroll
        for (int it = 0; it < 16; ++it) {
            int idx4 = tid + it * 256;           // 0..4095
            int tok = idx4 >> 6, ch4 = idx4 & 63;
            float4 v = src[idx4];
            int h = ch4 >> 3, c = (ch4 & 7) * 4;
            uint4 u = make_uint4(to_tf32(v.x), to_tf32(v.y), to_tf32(v.z), to_tf32(v.w));
            *(uint4*)(dynsmem + h * 6912 + m * 2304 + tok * 36 + c) = u;
        }
    }
    if (tid < 64) {
        int hs = ((wl >> 5) << 3) + (tid >> 3);
        int ws = ((wl & 31) << 3) + (tid & 7);
        int rh = (hs < 248) ? 0 : (hs < 252 ? 1 : 2);
        int rw = (ws < 248) ? 0 : (ws < 252 ? 1 : 2);
        sReg[tid] = rh * 3 + rw;
    }
    __syncthreads();

    const uint32_t* sQ = (const uint32_t*)(dynsmem + wid * 6912);
    const uint32_t* sK = sQ + 2304;
    const uint32_t* sV = sQ + 4608;
    float* sP = dynsmem + wid * 6912;           // overlays Q,K after S phase

    // ---- S = Q K^T (64x64), tf32 mma ----
    float accS[4][8][4];
#pragma unroll
    for (int i = 0; i < 4; ++i)
#pragma unroll
        for (int j = 0; j < 8; ++j)
#pragma unroll
            for (int c = 0; c < 4; ++c) accS[i][j][c] = 0.f;

#pragma unroll
    for (int ks = 0; ks < 4; ++ks) {
        uint32_t a[4][4];
#pragma unroll
        for (int mt = 0; mt < 4; ++mt) {
            const uint32_t* r0 = sQ + (mt * 16 + g) * 36 + ks * 8;
            a[mt][0] = r0[tig];
            a[mt][1] = r0[8 * 36 + tig];
            a[mt][2] = r0[tig + 4];
            a[mt][3] = r0[8 * 36 + tig + 4];
        }
#pragma unroll
        for (int nt = 0; nt < 8; ++nt) {
            const uint32_t* rb = sK + (nt * 8 + g) * 36 + ks * 8;
            uint32_t b0 = rb[tig], b1 = rb[tig + 4];
#pragma unroll
            for (int mt = 0; mt < 4; ++mt) mma_tf32(accS[mt][nt], a[mt], b0, b1);
        }
    }

    // scale + mask (mask only for edge windows)
    const bool edge = ((wl >> 5) == 31) || ((wl & 31) == 31);
#pragma unroll
    for (int mt = 0; mt < 4; ++mt)
#pragma unroll
        for (int nt = 0; nt < 8; ++nt)
#pragma unroll
            for (int c = 0; c < 4; ++c) accS[mt][nt][c] *= SCALE;
    if (edge) {
        int creg[2][8];
#pragma unroll
        for (int nt = 0; nt < 8; ++nt) {
            creg[0][nt] = sReg[nt * 8 + 2 * tig];
            creg[1][nt] = sReg[nt * 8 + 2 * tig + 1];
        }
#pragma unroll
        for (int mt = 0; mt < 4; ++mt)
#pragma unroll
            for (int e = 0; e < 2; ++e) {
                int rr = sReg[mt * 16 + e * 8 + g];
#pragma unroll
                for (int nt = 0; nt < 8; ++nt) {
                    if (creg[0][nt] != rr) accS[mt][nt][e * 2] -= 100.f;
                    if (creg[1][nt] != rr) accS[mt][nt][e * 2 + 1] -= 100.f;
                }
            }
    }

    // ---- softmax (rows split across quads) ----
    float inv[4][2];
#pragma unroll
    for (int mt = 0; mt < 4; ++mt) {
#pragma unroll
        for (int e = 0; e < 2; ++e) {
            float mx = -1e30f;
#pragma unroll
            for (int nt = 0; nt < 8; ++nt) {
                mx = fmaxf(mx, accS[mt][nt][e * 2]);
                mx = fmaxf(mx, accS[mt][nt][e * 2 + 1]);
            }
            mx = fmaxf(mx, __shfl_xor_sync(0xffffffffu, mx, 1));
            mx = fmaxf(mx, __shfl_xor_sync(0xffffffffu, mx, 2));
            float sum = 0.f;
#pragma unroll
            for (int nt = 0; nt < 8; ++nt) {
                float e0 = __expf(accS[mt][nt][e * 2] - mx);
                float e1 = __expf(accS[mt][nt][e * 2 + 1] - mx);
                accS[mt][nt][e * 2] = e0;
                accS[mt][nt][e * 2 + 1] = e1;
                sum += e0 + e1;
            }
            sum += __shfl_xor_sync(0xffffffffu, sum, 1);
            sum += __shfl_xor_sync(0xffffffffu, sum, 2);
            inv[mt][e] = 1.f / sum;
        }
    }

    // ---- write P (normalized, tf32) to smem [64][68] ----
#pragma unroll
    for (int mt = 0; mt < 4; ++mt)
#pragma unroll
        for (int e = 0; e < 2; ++e) {
            float iv = inv[mt][e];
            uint32_t* prow = (uint32_t*)(sP + (mt * 16 + e * 8 + g) * 68);
#pragma unroll
            for (int nt = 0; nt < 8; ++nt) {
                uint2 u = make_uint2(to_tf32(accS[mt][nt][e * 2] * iv),
                                     to_tf32(accS[mt][nt][e * 2 + 1] * iv));
                *(uint2*)(prow + nt * 8 + 2 * tig) = u;
            }
        }
    __syncwarp();

    // ---- O = P V (64x32), tf32 mma ----
    float accO[4][4][4];
#pragma unroll
    for (int i = 0; i < 4; ++i)
#pragma unroll
        for (int j = 0; j < 4; ++j)
#pragma unroll
            for (int c = 0; c < 4; ++c) accO[i][j][c] = 0.f;

    const uint32_t* sPu = (const uint32_t*)sP;
#pragma unroll
    for (int s = 0; s < 8; ++s) {
        uint32_t a[4][4];
#pragma unroll
        for (int mt = 0; mt < 4; ++mt) {
            const uint32_t* r0 = sPu + (mt * 16 + g) * 68 + s * 8;
            a[mt][0] = r0[tig];
            a[mt][1] = r0[8 * 68 + tig];
            a[mt][2] = r0[tig + 4];
            a[mt][3] = r0[8 * 68 + tig + 4];
        }
#pragma unroll
        for (int nt = 0; nt < 4; ++nt) {
            uint32_t b0 = sV[(s * 8 + tig) * 36 + nt * 8 + g];
            uint32_t b1 = sV[(s * 8 + tig + 4) * 36 + nt * 8 + g];
#pragma unroll
            for (int mt = 0; mt < 4; ++mt) mma_tf32(accO[mt][nt], a[mt], b0, b1);
        }
    }

    // ---- store O: unpartition + roll(-4,-4), pixel-major ----
    const int bimg = win >> 10;
#pragma unroll
    for (int mt = 0; mt < 4; ++mt) {
#pragma unroll
        for (int e = 0; e < 2; ++e) {
            int tok = mt * 16 + e * 8 + g;
            int hs = ((wl >> 5) << 3) + (tok >> 3);
            int ws = ((wl & 31) << 3) + (tok & 7);
            int h = (hs + 252) & 255;
            int w = (ws + 252) & 255;
            float* dst = g_o + (((size_t)bimg * IMG + h) * IMG + w) * DIM + wid * HD;
#pragma unroll
            for (int nt = 0; nt < 4; ++nt) {
                float2 v = make_float2(accO[mt][nt][e * 2], accO[mt][nt][e * 2 + 1]);
                *(float2*)(dst + nt * 8 + 2 * tig) = v;
            }
        }
    }
}

// ---------------------------------------------------------------------------

extern "C" void kernel_launch(void* const* d_in, const int* in_sizes, int n_in,
                              void* d_out, int out_size) {
    const float* x      = (const float*)d_in[0];
    const float* qkv_w  = (const float*)d_in[1];
    const float* proj_w = (const float*)d_in[2];
    const float* proj_b = (const float*)d_in[3];
    float* out = (float*)d_out;

    float* qkv_ptr = nullptr;
    float* o_ptr = nullptr;
    cudaGetSymbolAddress((void**)&qkv_ptr, g_qkv);
    cudaGetSymbolAddress((void**)&o_ptr, g_o);

    const int gemm_smem = (4 * 4608 + 4 * 9216) * 4;   // 221184 B
    const int attn_smem = 8 * 6912 * 4;                // 221184 B
    cudaFuncSetAttribute(mma_gemm<true>, cudaFuncAttributeMaxDynamicSharedMemorySize,
                         gemm_smem);
    cudaFuncSetAttribute(mma_gemm<false>, cudaFuncAttributeMaxDynamicSharedMemorySize,
                         gemm_smem);
    cudaFuncSetAttribute(attn_kernel, cudaFuncAttributeMaxDynamicSharedMemorySize,
                         attn_smem);

    // 1) qkv projection (tf32 mma.sync) + shift + window partition
    mma_gemm<true><<<dim3(NPIX / 128, 3), 256, gemm_smem>>>(x, qkv_w, nullptr, qkv_ptr);
    // 2) tensor-core shifted-window attention (+ unpartition + reverse shift)
    attn_kernel<<<BATCH * NWIN, 256, attn_smem>>>();
    // 3) output projection (tf32 mma.sync) + bias
    mma_gemm<false><<<dim3(NPIX / 128, 1), 256, gemm_smem>>>(o_ptr, proj_w, proj_b, out);
}

// round 5
// speedup vs baseline: 3.5427x; 1.0437x over previous
#include <cuda_runtime.h>
#include <cstdint>

#define DIM 256
#define HEADS 8
#define HD 32
#define N_TOK 64
#define IMG 256
#define BATCH 4
#define NWIN 1024
#define NPIX 262144
#define SCALE 0.17677669529663687f

// scratch (static device globals: allocation-free per harness rules)
__device__ __align__(256) float g_qkv[201326592];  // [4096 win][3][64 tok][256 ch]
__device__ __align__(256) float g_o[67108864];     // rounded-x, later attn output
__device__ __align__(256) float g_wq[196608];      // rounded qkv_w
__device__ __align__(256) float g_wp[65536];       // rounded proj_w

extern __shared__ float dynsmem[];

__device__ __forceinline__ uint32_t to_tf32(float x) {
    uint32_t r;
    asm("cvt.rna.tf32.f32 %0, %1;" : "=r"(r) : "f"(x));
    return r;
}

__device__ __forceinline__ void mma_tf32(float c[4], const uint32_t a[4],
                                         uint32_t b0, uint32_t b1) {
    asm volatile(
        "mma.sync.aligned.m16n8k8.row.col.f32.tf32.tf32.f32 "
        "{%0,%1,%2,%3}, {%4,%5,%6,%7}, {%8,%9}, {%0,%1,%2,%3};"
        : "+f"(c[0]), "+f"(c[1]), "+f"(c[2]), "+f"(c[3])
        : "r"(a[0]), "r"(a[1]), "r"(a[2]), "r"(a[3]), "r"(b0), "r"(b1));
}

__device__ __forceinline__ uint32_t smem_u32(const void* p) {
    uint32_t a;
    asm("{ .reg .u64 t; cvta.to.shared.u64 t, %1; cvt.u32.u64 %0, t; }"
        : "=r"(a) : "l"(p));
    return a;
}

#define CP_ASYNC16(dst_u32, src) \
    asm volatile("cp.async.cg.shared.global [%0], [%1], 16;" \
                 :: "r"(dst_u32), "l"(src) : "memory")
#define CP_COMMIT() asm volatile("cp.async.commit_group;" ::: "memory")
#define CP_WAIT(n)  asm volatile("cp.async.wait_group %0;" :: "n"(n) : "memory")

// ---------------------------------------------------------------------------
// elementwise tf32 rounding pass (hoists cvt out of GEMM inner loops)
// ---------------------------------------------------------------------------
__global__ __launch_bounds__(256) void round_kernel(const float4* __restrict__ in,
                                                    uint4* __restrict__ out, int n4) {
    int i = blockIdx.x * 256 + threadIdx.x;
    if (i < n4) {
        float4 v = in[i];
        out[i] = make_uint4(to_tf32(v.x), to_tf32(v.y), to_tf32(v.z), to_tf32(v.w));
    }
}

// ---------------------------------------------------------------------------
// tf32 mma.sync GEMM on pre-rounded inputs: C[m,n] = sum_k A[m,k]*B[n,k], K=256.
// CTA 128x256, 256 thr (8 warps, warp tile 64x64), cp.async 4-stage pipeline,
// smem rows padded to 36 floats. Inner loop: 1 LDS per HMMA (no cvt).
// QKV=true : scatter epilogue (roll+4 + window partition) into g_qkv
// QKV=false: bias epilogue, dense row-major store
// ---------------------------------------------------------------------------
template <bool QKV>
__global__ __launch_bounds__(256, 1)
void mma_gemm(const float* __restrict__ A, const float* __restrict__ Bw,
              const float* __restrict__ bias, float* __restrict__ C) {
    float* sA = dynsmem;                 // [4][128][36]
    float* sB = dynsmem + 4 * 128 * 36;  // [4][256][36]
    const uint32_t sA_u = smem_u32(sA);
    const uint32_t sB_u = smem_u32(sB);

    const int tid = threadIdx.x;
    const int wid = tid >> 5, lane = tid & 31;
    const int g = lane >> 2, tig = lane & 3;
    const int warp_m = wid & 1, warp_n = wid >> 1;
    const int m0 = blockIdx.x * 128, n0 = blockIdx.y * 256;
    const int ar0 = tid >> 3, ac4 = tid & 7;

    float acc[4][8][4];
#pragma unroll
    for (int i = 0; i < 4; ++i)
#pragma unroll
        for (int j = 0; j < 8; ++j)
#pragma unroll
            for (int c = 0; c < 4; ++c) acc[i][j][c] = 0.f;

    auto issue = [&](int s) {
        const int k0 = s * 32;
        const uint32_t ab = sA_u + (uint32_t)((s & 3) * 4608 + ac4 * 4) * 4u;
        const uint32_t bb = sB_u + (uint32_t)((s & 3) * 9216 + ac4 * 4) * 4u;
#pragma unroll
        for (int t = 0; t < 4; ++t)
            CP_ASYNC16(ab + (uint32_t)((ar0 + t * 32) * 36) * 4u,
                       A + (size_t)(m0 + ar0 + t * 32) * DIM + k0 + ac4 * 4);
#pragma unroll
        for (int t = 0; t < 8; ++t)
            CP_ASYNC16(bb + (uint32_t)((ar0 + t * 32) * 36) * 4u,
                       Bw + (size_t)(n0 + ar0 + t * 32) * DIM + k0 + ac4 * 4);
        CP_COMMIT();
    };

    issue(0); issue(1); issue(2);

#pragma unroll 1
    for (int s = 0; s < 8; ++s) {
        if (s < 6) { CP_WAIT(2); }
        else if (s == 6) { CP_WAIT(1); }
        else { CP_WAIT(0); }
        __syncthreads();
        if (s < 5) issue(s + 3);

        const uint32_t* bA = (const uint32_t*)(sA + (s & 3) * 4608 + warp_m * 64 * 36);
        const uint32_t* bB = (const uint32_t*)(sB + (s & 3) * 9216 + warp_n * 64 * 36);
#pragma unroll
        for (int k = 0; k < 32; k += 8) {
            uint32_t a[4][4];
#pragma unroll
            for (int mt = 0; mt < 4; ++mt) {
                const uint32_t* r0 = bA + (mt * 16 + g) * 36 + k;
                a[mt][0] = r0[tig];
                a[mt][1] = r0[8 * 36 + tig];
                a[mt][2] = r0[tig + 4];
                a[mt][3] = r0[8 * 36 + tig + 4];
            }
#pragma unroll
            for (int nt = 0; nt < 8; ++nt) {
                const uint32_t* rb = bB + (nt * 8 + g) * 36 + k;
                uint32_t b0 = rb[tig], b1 = rb[tig + 4];
#pragma unroll
                for (int mt = 0; mt < 4; ++mt) mma_tf32(acc[mt][nt], a[mt], b0, b1);
            }
        }
        __syncthreads();
    }

    // epilogue
#pragma unroll
    for (int mt = 0; mt < 4; ++mt) {
#pragma unroll
        for (int e = 0; e < 2; ++e) {
            int row = m0 + warp_m * 64 + mt * 16 + e * 8 + g;
            float* dst;
            if (QKV) {
                int b = row >> 16;
                int h = (row >> 8) & 255;
                int w = row & 255;
                int hs = (h + 4) & 255;
                int ws = (w + 4) & 255;
                int win = b * NWIN + ((hs >> 3) << 5) + (ws >> 3);
                int n = ((hs & 7) << 3) | (ws & 7);
                dst = C + (((size_t)win * 3 + blockIdx.y) * N_TOK + n) * DIM;
            } else {
                dst = C + (size_t)row * DIM;
            }
#pragma unroll
            for (int nt = 0; nt < 8; ++nt) {
                int col = warp_n * 64 + nt * 8 + 2 * tig;
                float2 v = make_float2(acc[mt][nt][e * 2], acc[mt][nt][e * 2 + 1]);
                if (!QKV) {
                    float2 bi = *(const float2*)(bias + col);
                    v.x += bi.x; v.y += bi.y;
                }
                *(float2*)(dst + col) = v;
            }
        }
    }
}

// ---------------------------------------------------------------------------
// Tensor-core windowed attention: 1 block per (window, head-group-of-4),
// 128 thr, warp w = head (hg*4 + w). Q,K,V cvt'd to tf32 in smem per head:
// [Q 64x36 | K 64x36 | V 64x36] (6912 floats/head, 110KB/block -> 2 CTA/SM).
// S = Q K^T and O = P V via m16n8k8 tf32 mma; register softmax; P overlays
// dead Q/K smem (64x68). Store fuses unpartition + roll(-4,-4), tf32-rounded.
// ---------------------------------------------------------------------------
__global__ __launch_bounds__(128, 2) void attn_kernel() {
    __shared__ int sReg[64];
    const int win = blockIdx.x >> 1;
    const int hg = blockIdx.x & 1;      // head group (4 heads)
    const int wl = win & 1023;
    const int tid = threadIdx.x;
    const int wid = tid >> 5, lane = tid & 31;
    const int g = lane >> 2, tig = lane & 3;

    const float* base = g_qkv + (size_t)win * 3 * N_TOK * DIM;

    // cooperative load + tf32 cvt: this head-group's channels of Q,K,V
#pragma unroll
    for (int m = 0; m < 3; ++m) {
        const float4* src = (const float4*)(base + m * N_TOK * DIM);
#pragma unroll
        for (int it = 0; it < 16; ++it) {
            int idx4 = tid + it * 128;           // 0..2047
            int tok = idx4 >> 5, ch4 = idx4 & 31;
            float4 v = src[tok * 64 + hg * 32 + ch4];
            int h = ch4 >> 3, c = (ch4 & 7) * 4;
            uint4 u = make_uint4(to_tf32(v.x), to_tf32(v.y), to_tf32(v.z), to_tf32(v.w));
            *(uint4*)(dynsmem + h * 6912 + m * 2304 + tok * 36 + c) = u;
        }
    }
    if (tid < 64) {
        int hs = ((wl >> 5) << 3) + (tid >> 3);
        int ws = ((wl & 31) << 3) + (tid & 7);
        int rh = (hs < 248) ? 0 : (hs < 252 ? 1 : 2);
        int rw = (ws < 248) ? 0 : (ws < 252 ? 1 : 2);
        sReg[tid] = rh * 3 + rw;
    }
    __syncthreads();

    const uint32_t* sQ = (const uint32_t*)(dynsmem + wid * 6912);
    const uint32_t* sK = sQ + 2304;
    const uint32_t* sV = sQ + 4608;
    float* sP = dynsmem + wid * 6912;           // overlays Q,K after S phase

    // ---- S = Q K^T (64x64) ----
    float accS[4][8][4];
#pragma unroll
    for (int i = 0; i < 4; ++i)
#pragma unroll
        for (int j = 0; j < 8; ++j)
#pragma unroll
            for (int c = 0; c < 4; ++c) accS[i][j][c] = 0.f;

#pragma unroll
    for (int ks = 0; ks < 4; ++ks) {
        uint32_t a[4][4];
#pragma unroll
        for (int mt = 0; mt < 4; ++mt) {
            const uint32_t* r0 = sQ + (mt * 16 + g) * 36 + ks * 8;
            a[mt][0] = r0[tig];
            a[mt][1] = r0[8 * 36 + tig];
            a[mt][2] = r0[tig + 4];
            a[mt][3] = r0[8 * 36 + tig + 4];
        }
#pragma unroll
        for (int nt = 0; nt < 8; ++nt) {
            const uint32_t* rb = sK + (nt * 8 + g) * 36 + ks * 8;
            uint32_t b0 = rb[tig], b1 = rb[tig + 4];
#pragma unroll
            for (int mt = 0; mt < 4; ++mt) mma_tf32(accS[mt][nt], a[mt], b0, b1);
        }
    }

    const bool edge = ((wl >> 5) == 31) || ((wl & 31) == 31);
#pragma unroll
    for (int mt = 0; mt < 4; ++mt)
#pragma unroll
        for (int nt = 0; nt < 8; ++nt)
#pragma unroll
            for (int c = 0; c < 4; ++c) accS[mt][nt][c] *= SCALE;
    if (edge) {
        int creg[2][8];
#pragma unroll
        for (int nt = 0; nt < 8; ++nt) {
            creg[0][nt] = sReg[nt * 8 + 2 * tig];
            creg[1][nt] = sReg[nt * 8 + 2 * tig + 1];
        }
#pragma unroll
        for (int mt = 0; mt < 4; ++mt)
#pragma unroll
            for (int e = 0; e < 2; ++e) {
                int rr = sReg[mt * 16 + e * 8 + g];
#pragma unroll
                for (int nt = 0; nt < 8; ++nt) {
                    if (creg[0][nt] != rr) accS[mt][nt][e * 2] -= 100.f;
                    if (creg[1][nt] != rr) accS[mt][nt][e * 2 + 1] -= 100.f;
                }
            }
    }

    // ---- softmax ----
    float inv[4][2];
#pragma unroll
    for (int mt = 0; mt < 4; ++mt) {
#pragma unroll
        for (int e = 0; e < 2; ++e) {
            float mx = -1e30f;
#pragma unroll
            for (int nt = 0; nt < 8; ++nt) {
                mx = fmaxf(mx, accS[mt][nt][e * 2]);
                mx = fmaxf(mx, accS[mt][nt][e * 2 + 1]);
            }
            mx = fmaxf(mx, __shfl_xor_sync(0xffffffffu, mx, 1));
            mx = fmaxf(mx, __shfl_xor_sync(0xffffffffu, mx, 2));
            float sum = 0.f;
#pragma unroll
            for (int nt = 0; nt < 8; ++nt) {
                float e0 = __expf(accS[mt][nt][e * 2] - mx);
                float e1 = __expf(accS[mt][nt][e * 2 + 1] - mx);
                accS[mt][nt][e * 2] = e0;
                accS[mt][nt][e * 2 + 1] = e1;
                sum += e0 + e1;
            }
            sum += __shfl_xor_sync(0xffffffffu, sum, 1);
            sum += __shfl_xor_sync(0xffffffffu, sum, 2);
            inv[mt][e] = 1.f / sum;
        }
    }

    // ---- write P (normalized, tf32) to smem [64][68] ----
#pragma unroll
    for (int mt = 0; mt < 4; ++mt)
#pragma unroll
        for (int e = 0; e < 2; ++e) {
            float iv = inv[mt][e];
            uint32_t* prow = (uint32_t*)(sP + (mt * 16 + e * 8 + g) * 68);
#pragma unroll
            for (int nt = 0; nt < 8; ++nt) {
                uint2 u = make_uint2(to_tf32(accS[mt][nt][e * 2] * iv),
                                     to_tf32(accS[mt][nt][e * 2 + 1] * iv));
                *(uint2*)(prow + nt * 8 + 2 * tig) = u;
            }
        }
    __syncwarp();

    // ---- O = P V (64x32) ----
    float accO[4][4][4];
#pragma unroll
    for (int i = 0; i < 4; ++i)
#pragma unroll
        for (int j = 0; j < 4; ++j)
#pragma unroll
            for (int c = 0; c < 4; ++c) accO[i][j][c] = 0.f;

    const uint32_t* sPu = (const uint32_t*)sP;
#pragma unroll
    for (int s = 0; s < 8; ++s) {
        uint32_t a[4][4];
#pragma unroll
        for (int mt = 0; mt < 4; ++mt) {
            const uint32_t* r0 = sPu + (mt * 16 + g) * 68 + s * 8;
            a[mt][0] = r0[tig];
            a[mt][1] = r0[8 * 68 + tig];
            a[mt][2] = r0[tig + 4];
            a[mt][3] = r0[8 * 68 + tig + 4];
        }
#pragma unroll
        for (int nt = 0; nt < 4; ++nt) {
            uint32_t b0 = sV[(s * 8 + tig) * 36 + nt * 8 + g];
            uint32_t b1 = sV[(s * 8 + tig + 4) * 36 + nt * 8 + g];
#pragma unroll
            for (int mt = 0; mt < 4; ++mt) mma_tf32(accO[mt][nt], a[mt], b0, b1);
        }
    }

    // ---- store O tf32-rounded (proj GEMM reads it cvt-free) ----
    const int bimg = win >> 10;
#pragma unroll
    for (int mt = 0; mt < 4; ++mt) {
#pragma unroll
        for (int e = 0; e < 2; ++e) {
            int tok = mt * 16 + e * 8 + g;
            int hs = ((wl >> 5) << 3) + (tok >> 3);
            int ws = ((wl & 31) << 3) + (tok & 7);
            int h = (hs + 252) & 255;
            int w = (ws + 252) & 255;
            float* dst = g_o + (((size_t)bimg * IMG + h) * IMG + w) * DIM +
                         (hg * 4 + wid) * HD;
#pragma unroll
            for (int nt = 0; nt < 4; ++nt) {
                float2 v = make_float2(
                    __uint_as_float(to_tf32(accO[mt][nt][e * 2])),
                    __uint_as_float(to_tf32(accO[mt][nt][e * 2 + 1])));
                *(float2*)(dst + nt * 8 + 2 * tig) = v;
            }
        }
    }
}

// ---------------------------------------------------------------------------

extern "C" void kernel_launch(void* const* d_in, const int* in_sizes, int n_in,
                              void* d_out, int out_size) {
    const float* x      = (const float*)d_in[0];
    const float* qkv_w  = (const float*)d_in[1];
    const float* proj_w = (const float*)d_in[2];
    const float* proj_b = (const float*)d_in[3];
    float* out = (float*)d_out;

    float* qkv_ptr = nullptr;
    float* o_ptr = nullptr;
    float* wq_ptr = nullptr;
    float* wp_ptr = nullptr;
    cudaGetSymbolAddress((void**)&qkv_ptr, g_qkv);
    cudaGetSymbolAddress((void**)&o_ptr, g_o);
    cudaGetSymbolAddress((void**)&wq_ptr, g_wq);
    cudaGetSymbolAddress((void**)&wp_ptr, g_wp);

    const int gemm_smem = (4 * 4608 + 4 * 9216) * 4;   // 221184 B
    const int attn_smem = 4 * 6912 * 4;                // 110592 B
    cudaFuncSetAttribute(mma_gemm<true>, cudaFuncAttributeMaxDynamicSharedMemorySize,
                         gemm_smem);
    cudaFuncSetAttribute(mma_gemm<false>, cudaFuncAttributeMaxDynamicSharedMemorySize,
                         gemm_smem);
    cudaFuncSetAttribute(attn_kernel, cudaFuncAttributeMaxDynamicSharedMemorySize,
                         attn_smem);

    // 0) tf32-round inputs (hoists cvt out of GEMM inner loops)
    round_kernel<<<NPIX * DIM / 4 / 256, 256>>>((const float4*)x, (uint4*)o_ptr,
                                                NPIX * DIM / 4);
    round_kernel<<<(196608 / 4 + 255) / 256, 256>>>((const float4*)qkv_w,
                                                    (uint4*)wq_ptr, 196608 / 4);
    round_kernel<<<(65536 / 4 + 255) / 256, 256>>>((const float4*)proj_w,
                                                   (uint4*)wp_ptr, 65536 / 4);

    // 1) qkv projection (cvt-free tf32 mma) + shift + window partition
    mma_gemm<true><<<dim3(NPIX / 128, 3), 256, gemm_smem>>>(o_ptr, wq_ptr, nullptr,
                                                            qkv_ptr);
    // 2) tensor-core shifted-window attention (+ unpartition + reverse shift)
    attn_kernel<<<BATCH * NWIN * 2, 128, attn_smem>>>();
    // 3) output projection (cvt-free tf32 mma) + bias
    mma_gemm<false><<<dim3(NPIX / 128, 1), 256, gemm_smem>>>(o_ptr, wp_ptr, proj_b, out);
}

// round 6
// speedup vs baseline: 5.5887x; 1.5775x over previous
#include <cuda_runtime.h>
#include <cuda_fp16.h>
#include <cstdint>

#define DIM 256
#define HEADS 8
#define HD 32
#define N_TOK 64
#define IMG 256
#define BATCH 4
#define NWIN 1024
#define NPIX 262144
#define SCALE 0.17677669529663687f

// scratch (static device globals: allocation-free per harness rules)
__device__ __align__(256) __half g_qkv[201326592];  // [4096 win][3][64 tok][256 ch]
__device__ __align__(256) __half g_o[67108864];     // rounded-x, later attn output
__device__ __align__(256) __half g_wq[196608];      // fp16 qkv_w
__device__ __align__(256) __half g_wp[65536];       // fp16 proj_w

extern __shared__ float dynsmem[];

__device__ __forceinline__ uint32_t pack_h2(float a, float b) {
    __half2 h = __floats2half2_rn(a, b);        // low = a, high = b
    uint32_t r;
    memcpy(&r, &h, 4);
    return r;
}

__device__ __forceinline__ void mma_f16(float c[4], const uint32_t a[4],
                                        uint32_t b0, uint32_t b1) {
    asm volatile(
        "mma.sync.aligned.m16n8k16.row.col.f32.f16.f16.f32 "
        "{%0,%1,%2,%3}, {%4,%5,%6,%7}, {%8,%9}, {%0,%1,%2,%3};"
        : "+f"(c[0]), "+f"(c[1]), "+f"(c[2]), "+f"(c[3])
        : "r"(a[0]), "r"(a[1]), "r"(a[2]), "r"(a[3]), "r"(b0), "r"(b1));
}

__device__ __forceinline__ uint32_t smem_u32(const void* p) {
    uint32_t a;
    asm("{ .reg .u64 t; cvta.to.shared.u64 t, %1; cvt.u32.u64 %0, t; }"
        : "=r"(a) : "l"(p));
    return a;
}

#define CP_ASYNC16(dst_u32, src) \
    asm volatile("cp.async.cg.shared.global [%0], [%1], 16;" \
                 :: "r"(dst_u32), "l"(src) : "memory")
#define CP_COMMIT() asm volatile("cp.async.commit_group;" ::: "memory")
#define CP_WAIT(n)  asm volatile("cp.async.wait_group %0;" :: "n"(n) : "memory")

// ---------------------------------------------------------------------------
// fp32 -> fp16 rounding pass (8 floats -> 8 halves per thread)
// ---------------------------------------------------------------------------
__global__ __launch_bounds__(256) void round_kernel(const float4* __restrict__ in,
                                                    uint4* __restrict__ out, int n8) {
    int i = blockIdx.x * 256 + threadIdx.x;
    if (i < n8) {
        float4 v0 = in[i * 2], v1 = in[i * 2 + 1];
        uint4 r;
        r.x = pack_h2(v0.x, v0.y);
        r.y = pack_h2(v0.z, v0.w);
        r.z = pack_h2(v1.x, v1.y);
        r.w = pack_h2(v1.z, v1.w);
        out[i] = r;
    }
}

// ---------------------------------------------------------------------------
// fp16 mma.sync GEMM: C[m,n] = sum_k A[m,k]*B[n,k], K=256, fp32 accum.
// CTA 128x256 (m0 = blockIdx.y*128, n0 = blockIdx.x*256), 256 thr, 8 warps
// with 64x64 warp tiles, cp.async 4-stage pipeline, 8 K-stages of 32.
// smem rows: 32 halves + pad -> stride 40 halves (20 words; bank 20g+tig all
// distinct). Inner loop: m16n8k16 HMMA, 1 LDS.32 per HMMA.
// QKV=true : fp16 scatter epilogue (roll+4 + window partition) into g_qkv
// QKV=false: fp32 bias epilogue, dense row-major store
// ---------------------------------------------------------------------------
template <bool QKV>
__global__ __launch_bounds__(256, 1)
void mma_gemm(const __half* __restrict__ A, const __half* __restrict__ Bw,
              const float* __restrict__ bias, void* __restrict__ Cv) {
    __half* sA = (__half*)dynsmem;          // [4][128][40] halves
    __half* sB = sA + 4 * 5120;             // [4][256][40] halves
    const uint32_t sA_u = smem_u32(sA);
    const uint32_t sB_u = smem_u32(sB);

    const int tid = threadIdx.x;
    const int wid = tid >> 5, lane = tid & 31;
    const int g = lane >> 2, tig = lane & 3;
    const int warp_m = wid & 1, warp_n = wid >> 1;
    const int m0 = blockIdx.y * 128, n0 = blockIdx.x * 256;

    float acc[4][8][4];
#pragma unroll
    for (int i = 0; i < 4; ++i)
#pragma unroll
        for (int j = 0; j < 8; ++j)
#pragma unroll
            for (int c = 0; c < 4; ++c) acc[i][j][c] = 0.f;

    auto issue = [&](int s) {
        const int k0 = s * 32;
#pragma unroll
        for (int j = 0; j < 2; ++j) {       // A: 512 16B chunks
            int c = tid + j * 256;
            int row = c >> 2, part = c & 3;
            CP_ASYNC16(sA_u + (uint32_t)((s & 3) * 5120 + row * 40 + part * 8) * 2u,
                       A + (size_t)(m0 + row) * DIM + k0 + part * 8);
        }
#pragma unroll
        for (int j = 0; j < 4; ++j) {       // B: 1024 16B chunks
            int c = tid + j * 256;
            int row = c >> 2, part = c & 3;
            CP_ASYNC16(sB_u + (uint32_t)((s & 3) * 10240 + row * 40 + part * 8) * 2u,
                       Bw + (size_t)(n0 + row) * DIM + k0 + part * 8);
        }
        CP_COMMIT();
    };

    issue(0); issue(1); issue(2);

#pragma unroll 1
    for (int s = 0; s < 8; ++s) {
        if (s < 6) { CP_WAIT(2); }
        else if (s == 6) { CP_WAIT(1); }
        else { CP_WAIT(0); }
        __syncthreads();
        if (s < 5) issue(s + 3);

        const uint32_t* uA = (const uint32_t*)sA + (s & 3) * 2560 + warp_m * 64 * 20;
        const uint32_t* uB = (const uint32_t*)sB + (s & 3) * 5120 + warp_n * 64 * 20;
#pragma unroll
        for (int kk = 0; kk < 2; ++kk) {
            uint32_t a[4][4];
#pragma unroll
            for (int mt = 0; mt < 4; ++mt) {
                const uint32_t* r0 = uA + (mt * 16 + g) * 20 + kk * 8;
                a[mt][0] = r0[tig];
                a[mt][1] = r0[8 * 20 + tig];
                a[mt][2] = r0[tig + 4];
                a[mt][3] = r0[8 * 20 + tig + 4];
            }
#pragma unroll
            for (int nt = 0; nt < 8; ++nt) {
                const uint32_t* rb = uB + (nt * 8 + g) * 20 + kk * 8;
                uint32_t b0 = rb[tig], b1 = rb[tig + 4];
#pragma unroll
                for (int mt = 0; mt < 4; ++mt) mma_f16(acc[mt][nt], a[mt], b0, b1);
            }
        }
        __syncthreads();
    }

    // epilogue
#pragma unroll
    for (int mt = 0; mt < 4; ++mt) {
#pragma unroll
        for (int e = 0; e < 2; ++e) {
            int row = m0 + warp_m * 64 + mt * 16 + e * 8 + g;
            if (QKV) {
                int b = row >> 16;
                int h = (row >> 8) & 255;
                int w = row & 255;
                int hs = (h + 4) & 255;        // cyclic shift +4
                int ws = (w + 4) & 255;
                int win = b * NWIN + ((hs >> 3) << 5) + (ws >> 3);
                int n = ((hs & 7) << 3) | (ws & 7);
                __half* dst = (__half*)Cv +
                              (((size_t)win * 3 + blockIdx.x) * N_TOK + n) * DIM;
#pragma unroll
                for (int nt = 0; nt < 8; ++nt) {
                    int col = warp_n * 64 + nt * 8 + 2 * tig;
                    uint32_t p = pack_h2(acc[mt][nt][e * 2], acc[mt][nt][e * 2 + 1]);
                    *(uint32_t*)(dst + col) = p;
                }
            } else {
                float* dst = (float*)Cv + (size_t)row * DIM;
#pragma unroll
                for (int nt = 0; nt < 8; ++nt) {
                    int col = warp_n * 64 + nt * 8 + 2 * tig;
                    float2 bi = *(const float2*)(bias + col);
                    float2 v = make_float2(acc[mt][nt][e * 2] + bi.x,
                                           acc[mt][nt][e * 2 + 1] + bi.y);
                    *(float2*)(dst + col) = v;
                }
            }
        }
    }
}

// ---------------------------------------------------------------------------
// fp16 tensor-core windowed attention: 1 block per (window, head-group-of-4),
// 128 thr, warp w = head hg*4+w. Per head smem (halves): Q [64][40] (2560),
// K [64][40] (2560), Vt [32][72] (2304, V stored TRANSPOSED at load so PV
// B-frags are aligned k-pairs), head stride 7440. P [64][72] overlays Q+K.
// S = Q K^T, O = P V via m16n8k16; register softmax; analytic Swin mask.
// Store fuses unpartition + roll(-4,-4) into pixel-major fp16 g_o.
// ---------------------------------------------------------------------------
__global__ __launch_bounds__(128, 2) void attn_kernel() {
    __shared__ int sReg[64];
    __half* smemh = (__half*)dynsmem;

    const int win = blockIdx.x >> 1;
    const int hg = blockIdx.x & 1;           // head group of 4
    const int wl = win & 1023;
    const int tid = threadIdx.x;
    const int wid = tid >> 5, lane = tid & 31;
    const int g = lane >> 2, tig = lane & 3;

    // cooperative load: Q,K copied; V transposed into Vt
#pragma unroll
    for (int m = 0; m < 3; ++m) {
        const uint4* src = (const uint4*)(g_qkv + ((size_t)win * 3 + m) * N_TOK * DIM);
#pragma unroll
        for (int it = 0; it < 8; ++it) {
            int idx = tid + it * 128;        // 0..1023
            int tok = idx >> 4, ch8 = idx & 15;
            uint4 v = src[tok * 32 + hg * 16 + ch8];
            int head = ch8 >> 2, c0 = (ch8 & 3) * 8;
            __half* hb = smemh + head * 7440;
            if (m < 2) {
                *(uint4*)(hb + m * 2560 + tok * 40 + c0) = v;
            } else {
                __half tmp[8];
                *(uint4*)tmp = v;
#pragma unroll
                for (int j = 0; j < 8; ++j) hb[5120 + (c0 + j) * 72 + tok] = tmp[j];
            }
        }
    }
    if (tid < 64) {
        int hs = ((wl >> 5) << 3) + (tid >> 3);
        int ws = ((wl & 31) << 3) + (tid & 7);
        int rh = (hs < 248) ? 0 : (hs < 252 ? 1 : 2);
        int rw = (ws < 248) ? 0 : (ws < 252 ? 1 : 2);
        sReg[tid] = rh * 3 + rw;
    }
    __syncthreads();

    const uint32_t* uQ = (const uint32_t*)(smemh + wid * 7440);
    const uint32_t* uK = uQ + 1280;
    const uint32_t* uV = uQ + 2560;
    __half* hP = smemh + wid * 7440;         // P overlays Q,K after S phase

    // ---- S = Q K^T (64x64) ----
    float accS[4][8][4];
#pragma unroll
    for (int i = 0; i < 4; ++i)
#pragma unroll
        for (int j = 0; j < 8; ++j)
#pragma unroll
            for (int c = 0; c < 4; ++c) accS[i][j][c] = 0.f;

#pragma unroll
    for (int kk = 0; kk < 2; ++kk) {
        uint32_t a[4][4];
#pragma unroll
        for (int mt = 0; mt < 4; ++mt) {
            const uint32_t* r0 = uQ + (mt * 16 + g) * 20 + kk * 8;
            a[mt][0] = r0[tig];
            a[mt][1] = r0[8 * 20 + tig];
            a[mt][2] = r0[tig + 4];
            a[mt][3] = r0[8 * 20 + tig + 4];
        }
#pragma unroll
        for (int nt = 0; nt < 8; ++nt) {
            const uint32_t* rb = uK + (nt * 8 + g) * 20 + kk * 8;
            uint32_t b0 = rb[tig], b1 = rb[tig + 4];
#pragma unroll
            for (int mt = 0; mt < 4; ++mt) mma_f16(accS[mt][nt], a[mt], b0, b1);
        }
    }

    const bool edge = ((wl >> 5) == 31) || ((wl & 31) == 31);
#pragma unroll
    for (int mt = 0; mt < 4; ++mt)
#pragma unroll
        for (int nt = 0; nt < 8; ++nt)
#pragma unroll
            for (int c = 0; c < 4; ++c) accS[mt][nt][c] *= SCALE;
    if (edge) {
        int creg[2][8];
#pragma unroll
        for (int nt = 0; nt < 8; ++nt) {
            creg[0][nt] = sReg[nt * 8 + 2 * tig];
            creg[1][nt] = sReg[nt * 8 + 2 * tig + 1];
        }
#pragma unroll
        for (int mt = 0; mt < 4; ++mt)
#pragma unroll
            for (int e = 0; e < 2; ++e) {
                int rr = sReg[mt * 16 + e * 8 + g];
#pragma unroll
                for (int nt = 0; nt < 8; ++nt) {
                    if (creg[0][nt] != rr) accS[mt][nt][e * 2] -= 100.f;
                    if (creg[1][nt] != rr) accS[mt][nt][e * 2 + 1] -= 100.f;
                }
            }
    }

    // ---- softmax ----
    float inv[4][2];
#pragma unroll
    for (int mt = 0; mt < 4; ++mt) {
#pragma unroll
        for (int e = 0; e < 2; ++e) {
            float mx = -1e30f;
#pragma unroll
            for (int nt = 0; nt < 8; ++nt) {
                mx = fmaxf(mx, accS[mt][nt][e * 2]);
                mx = fmaxf(mx, accS[mt][nt][e * 2 + 1]);
            }
            mx = fmaxf(mx, __shfl_xor_sync(0xffffffffu, mx, 1));
            mx = fmaxf(mx, __shfl_xor_sync(0xffffffffu, mx, 2));
            float sum = 0.f;
#pragma unroll
            for (int nt = 0; nt < 8; ++nt) {
                float e0 = __expf(accS[mt][nt][e * 2] - mx);
                float e1 = __expf(accS[mt][nt][e * 2 + 1] - mx);
                accS[mt][nt][e * 2] = e0;
                accS[mt][nt][e * 2 + 1] = e1;
                sum += e0 + e1;
            }
            sum += __shfl_xor_sync(0xffffffffu, sum, 1);
            sum += __shfl_xor_sync(0xffffffffu, sum, 2);
            inv[mt][e] = 1.f / sum;
        }
    }

    __syncwarp();   // all Q/K reads done before P overlays them
    // ---- write P (normalized fp16) to smem [64][72] ----
#pragma unroll
    for (int mt = 0; mt < 4; ++mt)
#pragma unroll
        for (int e = 0; e < 2; ++e) {
            float iv = inv[mt][e];
            __half* prow = hP + (mt * 16 + e * 8 + g) * 72;
#pragma unroll
            for (int nt = 0; nt < 8; ++nt) {
                uint32_t p = pack_h2(accS[mt][nt][e * 2] * iv,
                                     accS[mt][nt][e * 2 + 1] * iv);
                *(uint32_t*)(prow + nt * 8 + 2 * tig) = p;
            }
        }
    __syncwarp();

    // ---- O = P V (64x32) ----
    float accO[4][4][4];
#pragma unroll
    for (int i = 0; i < 4; ++i)
#pragma unroll
        for (int j = 0; j < 4; ++j)
#pragma unroll
            for (int c = 0; c < 4; ++c) accO[i][j][c] = 0.f;

    const uint32_t* uP = (const uint32_t*)hP;
#pragma unroll
    for (int kk = 0; kk < 4; ++kk) {
        uint32_t a[4][4];
#pragma unroll
        for (int mt = 0; mt < 4; ++mt) {
            const uint32_t* r0 = uP + (mt * 16 + g) * 36 + kk * 8;
            a[mt][0] = r0[tig];
            a[mt][1] = r0[8 * 36 + tig];
            a[mt][2] = r0[tig + 4];
            a[mt][3] = r0[8 * 36 + tig + 4];
        }
#pragma unroll
        for (int nt = 0; nt < 4; ++nt) {
            const uint32_t* rb = uV + (nt * 8 + g) * 36 + kk * 8;
            uint32_t b0 = rb[tig], b1 = rb[tig + 4];
#pragma unroll
            for (int mt = 0; mt < 4; ++mt) mma_f16(accO[mt][nt], a[mt], b0, b1);
        }
    }

    // ---- store O fp16: unpartition + roll(-4,-4), pixel-major ----
    const int bimg = win >> 10;
#pragma unroll
    for (int mt = 0; mt < 4; ++mt) {
#pragma unroll
        for (int e = 0; e < 2; ++e) {
            int tok = mt * 16 + e * 8 + g;
            int hs = ((wl >> 5) << 3) + (tok >> 3);
            int ws = ((wl & 31) << 3) + (tok & 7);
            int h = (hs + 252) & 255;
            int w = (ws + 252) & 255;
            __half* dst = g_o + (((size_t)bimg * IMG + h) * IMG + w) * DIM +
                          (hg * 4 + wid) * HD;
#pragma unroll
            for (int nt = 0; nt < 4; ++nt) {
                uint32_t p = pack_h2(accO[mt][nt][e * 2], accO[mt][nt][e * 2 + 1]);
                *(uint32_t*)(dst + nt * 8 + 2 * tig) = p;
            }
        }
    }
}

// ---------------------------------------------------------------------------

extern "C" void kernel_launch(void* const* d_in, const int* in_sizes, int n_in,
                              void* d_out, int out_size) {
    const float* x      = (const float*)d_in[0];
    const float* qkv_w  = (const float*)d_in[1];
    const float* proj_w = (const float*)d_in[2];
    const float* proj_b = (const float*)d_in[3];
    float* out = (float*)d_out;

    __half* qkv_ptr = nullptr;
    __half* o_ptr = nullptr;
    __half* wq_ptr = nullptr;
    __half* wp_ptr = nullptr;
    cudaGetSymbolAddress((void**)&qkv_ptr, g_qkv);
    cudaGetSymbolAddress((void**)&o_ptr, g_o);
    cudaGetSymbolAddress((void**)&wq_ptr, g_wq);
    cudaGetSymbolAddress((void**)&wp_ptr, g_wp);

    const int gemm_smem = 4 * (5120 + 10240) * 2;   // 122880 B
    const int attn_smem = 4 * 7440 * 2;             // 59520 B
    cudaFuncSetAttribute(mma_gemm<true>, cudaFuncAttributeMaxDynamicSharedMemorySize,
                         gemm_smem);
    cudaFuncSetAttribute(mma_gemm<false>, cudaFuncAttributeMaxDynamicSharedMemorySize,
                         gemm_smem);
    cudaFuncSetAttribute(attn_kernel, cudaFuncAttributeMaxDynamicSharedMemorySize,
                         attn_smem);

    // 0) fp16-round inputs
    round_kernel<<<NPIX * DIM / 8 / 256, 256>>>((const float4*)x, (uint4*)o_ptr,
                                                NPIX * DIM / 8);
    round_kernel<<<196608 / 8 / 256, 256>>>((const float4*)qkv_w, (uint4*)wq_ptr,
                                            196608 / 8);
    round_kernel<<<65536 / 8 / 256, 256>>>((const float4*)proj_w, (uint4*)wp_ptr,
                                           65536 / 8);

    // 1) qkv projection (fp16 mma) + shift + window partition
    //    grid (3, 2048): the 3 n-blocks sharing an x-tile are launch-adjacent
    mma_gemm<true><<<dim3(3, NPIX / 128), 256, gemm_smem>>>(o_ptr, wq_ptr, nullptr,
                                                            qkv_ptr);
    // 2) fp16 tensor-core shifted-window attention
    attn_kernel<<<BATCH * NWIN * 2, 128, attn_smem>>>();
    // 3) output projection (fp16 mma) + bias, fp32 out
    mma_gemm<false><<<dim3(1, NPIX / 128), 256, gemm_smem>>>(o_ptr, wp_ptr, proj_b,
                                                             out);
}